// round 15
// baseline (speedup 1.0000x reference)
#include <cuda_runtime.h>
#include <cuda_fp16.h>
#include <cstdint>
#include <math.h>

#define D      1024
#define BATCH  4
#define NSEQ   2048
#define MROWS  (BATCH*NSEQ)
#define BN     128
#define BMT    128
#define BK     64
#define NITER  (D/BK)        // 16
#define NSLAB  (D/16)        // 64 k16-slabs total
#define THREADS 128
#define STAGES 3

// ---------------- scratch (fp16 fragment-order packed operands) ----------------
__device__ uint32_t g_xA [MROWS*D/2];   // x packed as A  (16MB)
__device__ uint32_t g_xB [MROWS*D/2];   // x packed as B  (16MB, lane-contiguous layout)
__device__ uint32_t g_WkA[D*D/2];       // Wk packed as A (2MB)
__device__ uint32_t g_WqB[D*D/2];       // Wq packed as B (2MB)
__device__ uint32_t g_WmB[D*D/2];       // Wm' packed as B(2MB)
__device__ uint32_t g_TA [MROWS*D/2];   // T packed as A  (16MB)
__device__ float g_w1[D];               // Wq @ bk
__device__ float g_w2[D];               // Wk @ bq
__device__ float g_P [MROWS];           // scale*(x@w1 + c0)
__device__ float g_Q [MROWS];           // scale*(x@w2)
__device__ float g_u [MROWS];           // tanh(x@Wo + bo)
__device__ float g_c0;                  // bq . bk

__device__ __forceinline__ uint32_t f2h2(float lo, float hi) {
    uint32_t r; asm("cvt.rn.f16x2.f32 %0, %1, %2;" : "=r"(r) : "f"(hi), "f"(lo));
    return r;
}
__device__ __forceinline__ void cp16(uint32_t saddr, const void* g) {
    asm volatile("cp.async.cg.shared.global [%0], [%1], 16;" :: "r"(saddr), "l"(g) : "memory");
}
__device__ __forceinline__ void mma_f16(float c[4], const uint32_t a[4], const uint32_t b[2]) {
    asm volatile(
        "mma.sync.aligned.m16n8k16.row.col.f32.f16.f16.f32 "
        "{%0,%1,%2,%3}, {%4,%5,%6,%7}, {%8,%9}, {%0,%1,%2,%3};"
        : "+f"(c[0]), "+f"(c[1]), "+f"(c[2]), "+f"(c[3])
        : "r"(a[0]), "r"(a[1]), "r"(a[2]), "r"(a[3]), "r"(b[0]), "r"(b[1]));
}

// division-free reciprocal for d in (0, 2): magic seed + 2 Newton steps (no MUFU).
__device__ __forceinline__ float frcp(float d) {
    float y = __uint_as_float(0x7EF311C3u - __float_as_uint(d));
    y = y * fmaf(-d, y, 2.0f);
    y = y * fmaf(-d, y, 2.0f);
    return y;
}

// ---------------- pack helpers ----------------
// A layout (unchanged): word = (k>>4)*(R/16)*128 + (m>>4)*128 + lane*4-group ...
__device__ __forceinline__ void pack_tile_A(const float s[128][36], uint32_t* dst, int R,
                                            int r0, int c0, int w, int l) {
    #pragma unroll
    for (int jj = 0; jj < 2; jj++) {
        int bi = w * 2 + jj;               // 0..15
        int mb = bi & 7, kb = bi >> 3;
        int mr = mb * 16 + (l >> 2);
        int kc = kb * 16 + (l & 3) * 2;
        uint4 v;
        v.x = f2h2(s[mr][kc],       s[mr][kc + 1]);
        v.y = f2h2(s[mr + 8][kc],   s[mr + 8][kc + 1]);
        v.z = f2h2(s[mr][kc + 8],   s[mr][kc + 9]);
        v.w = f2h2(s[mr + 8][kc + 8], s[mr + 8][kc + 9]);
        size_t blk = (size_t)((c0 >> 4) + kb) * (R / 16) + (r0 >> 4) + mb;
        *(uint4*)(dst + blk * 128 + l * 4) = v;
    }
}
// NEW lane-contiguous B layout:
//   word = ((slab*(R/64) + (n>>6))*32 + lane)*16 + ((n>>3)&7)*2 + e
//   lane = (n&7)*4 + ((k&7)>>1), e = (k>>3)&1  (k within slab)
// A warp's 8 tn-fragments for one slab are 16 contiguous words per lane.
__device__ __forceinline__ void pack_tile_B(const float s[128][36], uint32_t* dst, int R,
                                            int r0, int c0, int w, int l) {
    int kb  = w >> 2;                      // local slab 0..1
    int nb0 = (w & 3) * 4;                 // first local nb of this warp's 4
    uint32_t vals[8];
    #pragma unroll
    for (int jj = 0; jj < 4; jj++) {
        int nb = nb0 + jj;
        int nr = nb * 8 + (l >> 2);
        int kc = kb * 16 + (l & 3) * 2;
        vals[jj * 2 + 0] = f2h2(s[nr][kc],     s[nr][kc + 1]);
        vals[jj * 2 + 1] = f2h2(s[nr][kc + 8], s[nr][kc + 9]);
    }
    int nb_g   = (r0 >> 3) + nb0;
    int g      = nb_g >> 3;
    int t0     = nb_g & 7;                 // 0 or 4
    int slab_g = (c0 >> 4) + kb;
    size_t base = ((size_t)(slab_g * (R / 64) + g) * 32 + l) * 16 + t0 * 2;
    *(uint4*)(dst + base)     = *(uint4*)(vals);
    *(uint4*)(dst + base + 4) = *(uint4*)(vals + 4);
}
__device__ __forceinline__ void load_tile(const float* __restrict__ src, float s[128][36],
                                          int r0, int c0, int tid) {
    #pragma unroll
    for (int j = 0; j < 4; j++) {
        int idx = tid + j * 256;
        int r = idx >> 3, c4 = (idx & 7) * 4;
        *(float4*)&s[r][c4] = *(const float4*)(src + (size_t)(r0 + r) * D + c0 + c4);
    }
}

// fused: read x tile once, emit both layouts
__global__ void pack_x(const float* __restrict__ src, uint32_t* __restrict__ dstA,
                       uint32_t* __restrict__ dstB) {
    __shared__ float s[128][36];
    int tid = threadIdx.x, r0 = blockIdx.x * 128, c0 = blockIdx.y * 32;
    load_tile(src, s, r0, c0, tid);
    __syncthreads();
    pack_tile_A(s, dstA, MROWS, r0, c0, tid >> 5, tid & 31);
    pack_tile_B(s, dstB, MROWS, r0, c0, tid >> 5, tid & 31);
}
// weights: z=0 -> Wk as A, z=1 -> Wq as B (one launch)
__global__ void pack_w(const float* __restrict__ Wk, const float* __restrict__ Wq,
                       uint32_t* __restrict__ dstA, uint32_t* __restrict__ dstB) {
    __shared__ float s[128][36];
    int tid = threadIdx.x, r0 = blockIdx.x * 128, c0 = blockIdx.y * 32;
    if (blockIdx.z == 0) {
        load_tile(Wk, s, r0, c0, tid);
        __syncthreads();
        pack_tile_A(s, dstA, D, r0, c0, tid >> 5, tid & 31);
    } else {
        load_tile(Wq, s, r0, c0, tid);
        __syncthreads();
        pack_tile_B(s, dstB, D, r0, c0, tid >> 5, tid & 31);
    }
}

// ---------------- small vector kernels ----------------
__global__ void vecs_kernel(const float* __restrict__ Wq, const float* __restrict__ Wk,
                            const float* __restrict__ bq, const float* __restrict__ bk) {
    int gw   = (blockIdx.x * blockDim.x + threadIdx.x) >> 5;
    int lane = threadIdx.x & 31;
    float acc = 0.f;
    if (gw < D) {
        const float* row = Wq + (size_t)gw * D;
        for (int k = lane; k < D; k += 32) acc += row[k] * bk[k];
        #pragma unroll
        for (int o = 16; o > 0; o >>= 1) acc += __shfl_down_sync(0xffffffffu, acc, o);
        if (lane == 0) g_w1[gw] = acc;
    } else if (gw < 2*D) {
        const float* row = Wk + (size_t)(gw - D) * D;
        for (int k = lane; k < D; k += 32) acc += row[k] * bq[k];
        #pragma unroll
        for (int o = 16; o > 0; o >>= 1) acc += __shfl_down_sync(0xffffffffu, acc, o);
        if (lane == 0) g_w2[gw - D] = acc;
    } else if (gw == 2*D) {
        for (int k = lane; k < D; k += 32) acc += bq[k] * bk[k];
        #pragma unroll
        for (int o = 16; o > 0; o >>= 1) acc += __shfl_down_sync(0xffffffffu, acc, o);
        if (lane == 0) g_c0 = acc;
    }
}

__global__ void rows_kernel(const float* __restrict__ x, const float* __restrict__ Wo,
                            const float* __restrict__ bo) {
    int gw   = (blockIdx.x * blockDim.x + threadIdx.x) >> 5;
    int lane = threadIdx.x & 31;
    if (gw >= MROWS) return;
    const float* row = x + (size_t)gw * D;
    float ss = 0.f, pp = 0.f, qq = 0.f;
    for (int k = lane; k < D; k += 32) {
        float xv = row[k];
        ss += xv * Wo[k];
        pp += xv * g_w1[k];
        qq += xv * g_w2[k];
    }
    #pragma unroll
    for (int o = 16; o > 0; o >>= 1) {
        ss += __shfl_down_sync(0xffffffffu, ss, o);
        pp += __shfl_down_sync(0xffffffffu, pp, o);
        qq += __shfl_down_sync(0xffffffffu, qq, o);
    }
    if (lane == 0) {
        const float scale = 0.03125f;
        g_u[gw] = tanhf(ss + bo[0]);
        g_P[gw] = scale * (pp + g_c0);
        g_Q[gw] = scale * qq;
    }
}

// ---- fp16 GEMM: A via smem (cp.async, 3 stages), B via direct LDG.128 from L2
//      (lane-contiguous layout) with distance-3 register prefetch (ring of 4 slots).
// MODE 0: write C as B-packed fp16 (R_out = D).     [Wm']
// MODE 1: write C as A-packed fp16 (R_out = MROWS). [T]
// MODE 2: fused epilogue, row-major fp32 out, batched over blockIdx.z.
template<int MODE>
__global__ void __launch_bounds__(THREADS, 2) mm_kernel(
    const uint32_t* __restrict__ Apk, const uint32_t* __restrict__ Bpk,
    void* __restrict__ Cout, int strideA, int strideB)
{
    constexpr int KSLAB_A = (BMT / 16) * 128;   // 1024 words per k16-slab
    constexpr int ATW = 4 * KSLAB_A;            // BK=64 -> 4 slabs = 16KB/stage
    constexpr int TN = 8;                       // 2x2 warp grid, 64x64 warp tile

    extern __shared__ uint32_t sm[];
    const int tid = threadIdx.x, w = tid >> 5, lane = tid & 31;
    const int wm = (w >> 1) * 64;
    const int wn = (w & 1) * 64;
    const int zrow = (MODE == 2) ? blockIdx.z * NSEQ : 0;
    const int m0 = blockIdx.y * BMT, n0 = blockIdx.x * BN;
    const int brow0 = zrow + n0;

    const uint32_t* Abase = Apk + (size_t)((zrow + m0) >> 4) * 128;
    const int mblk0 = wm >> 4, nblk0 = wn >> 3;
    const int g0 = ((brow0 >> 3) + nblk0) >> 3;
    const uint32_t* Bf = Bpk + ((size_t)g0 * 32 + lane) * 16;
    uint32_t smbase = (uint32_t)__cvta_generic_to_shared(sm);

    float acc[4][TN][4] = {};
    uint32_t bfr[4][TN][2];                      // B frag ring, slot = slab & 3

    auto ldB = [&](int slot, int slab) {
        const uint4* p = (const uint4*)(Bf + (size_t)slab * strideB);
        uint4 q0 = __ldg(p + 0);
        uint4 q1 = __ldg(p + 1);
        uint4 q2 = __ldg(p + 2);
        uint4 q3 = __ldg(p + 3);
        bfr[slot][0][0] = q0.x; bfr[slot][0][1] = q0.y;
        bfr[slot][1][0] = q0.z; bfr[slot][1][1] = q0.w;
        bfr[slot][2][0] = q1.x; bfr[slot][2][1] = q1.y;
        bfr[slot][3][0] = q1.z; bfr[slot][3][1] = q1.w;
        bfr[slot][4][0] = q2.x; bfr[slot][4][1] = q2.y;
        bfr[slot][5][0] = q2.z; bfr[slot][5][1] = q2.w;
        bfr[slot][6][0] = q3.x; bfr[slot][6][1] = q3.y;
        bfr[slot][7][0] = q3.z; bfr[slot][7][1] = q3.w;
    };

    auto issueA = [&](int it, int st) {
        uint32_t sb = smbase + (uint32_t)(st * ATW) * 4u;
        constexpr int ACH = KSLAB_A / 4;        // 256 16B-chunks per slab
        #pragma unroll
        for (int j = 0; j < (4 * ACH) / THREADS; j++) {
            int idx = tid + j * THREADS;
            int kk = idx / ACH, off = idx % ACH;
            cp16(sb + (uint32_t)(kk * KSLAB_A + off * 4) * 4u,
                 Abase + (size_t)(it * 4 + kk) * strideA + off * 4);
        }
        asm volatile("cp.async.commit_group;" ::: "memory");
    };

    issueA(0, 0);
    issueA(1, 1);
    ldB(0, 0);
    ldB(1, 1);
    ldB(2, 2);

    for (int it = 0; it < NITER; it++) {
        int st = it % STAGES;
        if (it < NITER - 1) asm volatile("cp.async.wait_group 1;" ::: "memory");
        else                asm volatile("cp.async.wait_group 0;" ::: "memory");
        __syncthreads();
        if (it + 2 < NITER) issueA(it + 2, (it + 2) % STAGES);
        const uint32_t* base = sm + st * ATW;
        #pragma unroll
        for (int ks = 0; ks < 4; ks++) {
            // prefetch B for slab+3 into slot (ks+3)&3 (last used at slab-1, drained)
            int pf = it * 4 + ks + 3;
            if (pf > NSLAB - 1) pf = NSLAB - 1;
            ldB((ks + 3) & 3, pf);
            uint32_t afr[4][4];
            #pragma unroll
            for (int tm = 0; tm < 4; tm++)
                *(uint4*)afr[tm] = *(const uint4*)&base[ks * KSLAB_A + (mblk0 + tm) * 128 + lane * 4];
            #pragma unroll
            for (int tm = 0; tm < 4; tm++)
                #pragma unroll
                for (int tn = 0; tn < TN; tn++)
                    mma_f16(acc[tm][tn], afr[tm], bfr[ks & 3][tn]);
        }
        // no trailing barrier: issueA(it+2) targets stage (it-1)%3, already drained
        // by every warp having passed this iteration's top barrier.
    }

    // ---- epilogue ----
    if (MODE == 0) {
        // B-packed fp16 out (NEW layout), n = r, k = c
        uint32_t* Cd = (uint32_t*)Cout;
        #pragma unroll
        for (int tm = 0; tm < 4; tm++)
            #pragma unroll
            for (int tn = 0; tn < TN; tn++) {
                int r = m0 + wm + tm * 16 + (lane >> 2);
                int c = n0 + wn + tn * 8 + (lane & 3) * 2;
                uint32_t w0 = f2h2(acc[tm][tn][0], acc[tm][tn][1]);
                uint32_t w1 = f2h2(acc[tm][tn][2], acc[tm][tn][3]);
                int slab = c >> 4, e = (c >> 3) & 1;
                int lf = (r & 7) * 4 + ((c & 7) >> 1);
                int r8 = r + 8;
                int lf8 = (r8 & 7) * 4 + ((c & 7) >> 1);
                size_t wi0 = ((size_t)(slab * (D/64) + (r  >> 6)) * 32 + lf ) * 16
                           + ((r  >> 3) & 7) * 2 + e;
                size_t wi1 = ((size_t)(slab * (D/64) + (r8 >> 6)) * 32 + lf8) * 16
                           + ((r8 >> 3) & 7) * 2 + e;
                Cd[wi0] = w0;
                Cd[wi1] = w1;
            }
    } else if (MODE == 1) {
        // A-packed fp16 out (unchanged layout), m = r, k = c
        uint32_t* Cd = (uint32_t*)Cout;
        #pragma unroll
        for (int tm = 0; tm < 4; tm++)
            #pragma unroll
            for (int tn = 0; tn < TN; tn++) {
                int r = m0 + wm + tm * 16 + (lane >> 2);
                int c = n0 + wn + tn * 8 + (lane & 3) * 2;
                uint32_t w0 = f2h2(acc[tm][tn][0], acc[tm][tn][1]);
                uint32_t w1 = f2h2(acc[tm][tn][2], acc[tm][tn][3]);
                size_t kslab = (size_t)(c >> 4) * (MROWS / 16) * 128;
                int sub = ((c & 7) >> 1) * 4 + ((c & 8) >> 3) * 2;
                int r8 = r + 8;
                Cd[kslab + (size_t)(r  >> 4) * 128 + (r  & 7) * 16 + sub + ((r  & 8) >> 3)] = w0;
                Cd[kslab + (size_t)(r8 >> 4) * 128 + (r8 & 7) * 16 + sub + ((r8 & 8) >> 3)] = w1;
            }
    } else {
        float* C = (float*)Cout;
        float* sQ = (float*)sm;
        float* sU = sQ + BN;
        int jg0 = zrow + n0;
        __syncthreads();
        if (tid < BN) { sQ[tid] = g_Q[jg0 + tid]; sU[tid] = g_u[jg0 + tid]; }
        __syncthreads();
        const float scale = 0.03125f;
        size_t zr = (size_t)zrow;
        #pragma unroll
        for (int tm = 0; tm < 4; tm++) {
            int rloc0 = m0 + wm + tm * 16 + (lane >> 2);
            int rg0 = (int)zr + rloc0;
            float P0 = g_P[rg0],     u0 = g_u[rg0];
            float P1 = g_P[rg0 + 8], u1 = g_u[rg0 + 8];
            float* c0p = C + (zr + rloc0) * (size_t)NSEQ + n0;
            float* c1p = C + (zr + rloc0 + 8) * (size_t)NSEQ + n0;
            #pragma unroll
            for (int tn = 0; tn < TN; tn++) {
                int jl = wn + tn * 8 + (lane & 3) * 2;
                float qa = sQ[jl],   ua = sU[jl];
                float qb = sQ[jl+1], ub = sU[jl+1];
                float v00 = fmaf(scale, acc[tm][tn][0], P0 + qa)
                          + 5.f * (ua - u0) * frcp(fmaf(-u0, ua, 1.f));
                float v01 = fmaf(scale, acc[tm][tn][1], P0 + qb)
                          + 5.f * (ub - u0) * frcp(fmaf(-u0, ub, 1.f));
                float v10 = fmaf(scale, acc[tm][tn][2], P1 + qa)
                          + 5.f * (ua - u1) * frcp(fmaf(-u1, ua, 1.f));
                float v11 = fmaf(scale, acc[tm][tn][3], P1 + qb)
                          + 5.f * (ub - u1) * frcp(fmaf(-u1, ub, 1.f));
                *(float2*)(c0p + jl) = make_float2(v00, v01);
                *(float2*)(c1p + jl) = make_float2(v10, v11);
            }
        }
    }
}

// ---------------- launch (multi-stream DAG, monolithic GEMMs) ----------------
extern "C" void kernel_launch(void* const* d_in, const int* in_sizes, int n_in,
                              void* d_out, int out_size) {
    const float* x  = (const float*)d_in[0];
    const float* Wq = (const float*)d_in[1];
    const float* bq = (const float*)d_in[2];
    const float* Wk = (const float*)d_in[3];
    const float* bk = (const float*)d_in[4];
    const float* Wo = (const float*)d_in[5];
    const float* bo = (const float*)d_in[6];
    float* out = (float*)d_out;

    uint32_t *pxA, *pxB, *pWkA, *pWqB, *pWmB, *pTA;
    cudaGetSymbolAddress((void**)&pxA,  g_xA);
    cudaGetSymbolAddress((void**)&pxB,  g_xB);
    cudaGetSymbolAddress((void**)&pWkA, g_WkA);
    cudaGetSymbolAddress((void**)&pWqB, g_WqB);
    cudaGetSymbolAddress((void**)&pWmB, g_WmB);
    cudaGetSymbolAddress((void**)&pTA,  g_TA);

    const int SMK = STAGES * 4 * (BMT/16) * 128 * 4;  // 49152 (A stages only)
    static bool attr_done = false;
    if (!attr_done) {
        cudaFuncSetAttribute(mm_kernel<0>, cudaFuncAttributeMaxDynamicSharedMemorySize, SMK);
        cudaFuncSetAttribute(mm_kernel<1>, cudaFuncAttributeMaxDynamicSharedMemorySize, SMK);
        cudaFuncSetAttribute(mm_kernel<2>, cudaFuncAttributeMaxDynamicSharedMemorySize, SMK);
        attr_done = true;
    }

    // side streams + events for capture-safe fork/join (created once; first call is
    // the uncaptured correctness run; every call records the identical DAG)
    static cudaStream_t s1 = nullptr, s2 = nullptr;
    static cudaEvent_t  eRoot = nullptr, eG0 = nullptr, ePX = nullptr;
    if (!s1) {
        cudaStreamCreateWithFlags(&s1, cudaStreamNonBlocking);
        cudaStreamCreateWithFlags(&s2, cudaStreamNonBlocking);
        cudaEventCreateWithFlags(&eRoot, cudaEventDisableTiming);
        cudaEventCreateWithFlags(&eG0,   cudaEventDisableTiming);
        cudaEventCreateWithFlags(&ePX,   cudaEventDisableTiming);
    }
    cudaStream_t s0 = 0;   // harness (capture) stream

    // fork
    cudaEventRecord(eRoot, s0);
    cudaStreamWaitEvent(s1, eRoot, 0);
    cudaStreamWaitEvent(s2, eRoot, 0);

    // branch 1: weight pack -> GEMM0 (Wm' = Wk @ Wq^T, B-packed new layout)
    pack_w<<<dim3(D/128, D/32, 2), 256, 0, s1>>>(Wk, Wq, pWkA, pWqB);
    mm_kernel<0><<<dim3(D/BN, D/BMT), THREADS, SMK, s1>>>(pWkA, pWqB, pWmB, D*8, D*8);
    cudaEventRecord(eG0, s1);

    // branch 2: x pack (both layouts)
    pack_x<<<dim3(MROWS/128, D/32), 256, 0, s2>>>(x, pxA, pxB);
    cudaEventRecord(ePX, s2);

    // main: bias precompute (vecs -> rows)
    vecs_kernel<<<257, 256, 0, s0>>>(Wq, Wk, bq, bk);
    rows_kernel<<<1024, 256, 0, s0>>>(x, Wo, bo);

    // join: GEMM1 needs GEMM0 + pack_x(A); GEMM2 additionally needs rows (main-ordered)
    cudaStreamWaitEvent(s0, eG0, 0);
    cudaStreamWaitEvent(s0, ePX, 0);

    // T = x @ Wm (via Wm' as B), written A-packed
    mm_kernel<1><<<dim3(D/BN, MROWS/BMT), THREADS, SMK, s0>>>(pxA, pWmB, pTA, MROWS*8, D*8);
    // out[b,i,j] = scale*(T_b[i,:].x_b[j,:]) + P_i + Q_j + 5*tanh-identity
    mm_kernel<2><<<dim3(NSEQ/BN, NSEQ/BMT, BATCH), THREADS, SMK, s0>>>(
        pTA, pxB, out, MROWS*8, MROWS*8);
}

// round 17
// speedup vs baseline: 1.2350x; 1.2350x over previous
#include <cuda_runtime.h>
#include <cuda_fp16.h>
#include <cstdint>
#include <math.h>

#define D      1024
#define BATCH  4
#define NSEQ   2048
#define MROWS  (BATCH*NSEQ)
#define BN     128
#define BMT    128
#define BK     64
#define NITER  (D/BK)        // 16
#define NSLAB  (D/16)        // 64 k16-slabs total
#define THREADS 128
#define STAGES 3

// ---------------- scratch (fp16 fragment-order packed operands) ----------------
__device__ uint32_t g_xA [MROWS*D/2];   // x packed as A  (16MB)
__device__ uint32_t g_xB [MROWS*D/2];   // x packed as B  (16MB)
__device__ uint32_t g_WkA[D*D/2];       // Wk packed as A (2MB)
__device__ uint32_t g_WqB[D*D/2];       // Wq packed as B (2MB)
__device__ uint32_t g_WmB[D*D/2];       // Wm' packed as B(2MB)
__device__ uint32_t g_TA [MROWS*D/2];   // T packed as A  (16MB)
__device__ float g_w1[D];               // Wq @ bk
__device__ float g_w2[D];               // Wk @ bq
__device__ float g_P [MROWS];           // scale*(x@w1 + c0)
__device__ float g_Q [MROWS];           // scale*(x@w2)
__device__ float g_u [MROWS];           // tanh(x@Wo + bo)
__device__ float g_c0;                  // bq . bk

__device__ __forceinline__ uint32_t f2h2(float lo, float hi) {
    uint32_t r; asm("cvt.rn.f16x2.f32 %0, %1, %2;" : "=r"(r) : "f"(hi), "f"(lo));
    return r;
}
__device__ __forceinline__ void cp16(uint32_t saddr, const void* g) {
    asm volatile("cp.async.cg.shared.global [%0], [%1], 16;" :: "r"(saddr), "l"(g) : "memory");
}
__device__ __forceinline__ void mma_f16(float c[4], const uint32_t a[4], const uint32_t b[2]) {
    asm volatile(
        "mma.sync.aligned.m16n8k16.row.col.f32.f16.f16.f32 "
        "{%0,%1,%2,%3}, {%4,%5,%6,%7}, {%8,%9}, {%0,%1,%2,%3};"
        : "+f"(c[0]), "+f"(c[1]), "+f"(c[2]), "+f"(c[3])
        : "r"(a[0]), "r"(a[1]), "r"(a[2]), "r"(a[3]), "r"(b[0]), "r"(b[1]));
}

// division-free reciprocal for d in (0, 2): magic seed + 2 Newton steps (no MUFU).
__device__ __forceinline__ float frcp(float d) {
    float y = __uint_as_float(0x7EF311C3u - __float_as_uint(d));
    y = y * fmaf(-d, y, 2.0f);
    y = y * fmaf(-d, y, 2.0f);
    return y;
}

// ---------------- pack helpers: fp32 tile (128x32 smem) -> fp16 fragment order ------
__device__ __forceinline__ void pack_tile_A(const float s[128][36], uint32_t* dst, int R,
                                            int r0, int c0, int w, int l) {
    #pragma unroll
    for (int jj = 0; jj < 2; jj++) {
        int bi = w * 2 + jj;               // 0..15
        int mb = bi & 7, kb = bi >> 3;
        int mr = mb * 16 + (l >> 2);
        int kc = kb * 16 + (l & 3) * 2;
        uint4 v;
        v.x = f2h2(s[mr][kc],       s[mr][kc + 1]);
        v.y = f2h2(s[mr + 8][kc],   s[mr + 8][kc + 1]);
        v.z = f2h2(s[mr][kc + 8],   s[mr][kc + 9]);
        v.w = f2h2(s[mr + 8][kc + 8], s[mr + 8][kc + 9]);
        size_t blk = (size_t)((c0 >> 4) + kb) * (R / 16) + (r0 >> 4) + mb;
        *(uint4*)(dst + blk * 128 + l * 4) = v;
    }
}
__device__ __forceinline__ void pack_tile_B(const float s[128][36], uint32_t* dst, int R,
                                            int r0, int c0, int w, int l) {
    #pragma unroll
    for (int jj = 0; jj < 4; jj++) {
        int bi = w * 4 + jj;               // 0..31
        int nb = bi & 15, kb = bi >> 4;
        int nr = nb * 8 + (l >> 2);
        int kc = kb * 16 + (l & 3) * 2;
        uint2 v;
        v.x = f2h2(s[nr][kc],     s[nr][kc + 1]);
        v.y = f2h2(s[nr][kc + 8], s[nr][kc + 9]);
        size_t blk = (size_t)((c0 >> 4) + kb) * (R / 8) + (r0 >> 3) + nb;
        *(uint2*)(dst + blk * 64 + l * 2) = v;
    }
}
__device__ __forceinline__ void load_tile(const float* __restrict__ src, float s[128][36],
                                          int r0, int c0, int tid) {
    #pragma unroll
    for (int j = 0; j < 4; j++) {
        int idx = tid + j * 256;
        int r = idx >> 3, c4 = (idx & 7) * 4;
        *(float4*)&s[r][c4] = *(const float4*)(src + (size_t)(r0 + r) * D + c0 + c4);
    }
}

// fused: read x tile once, emit both layouts
__global__ void pack_x(const float* __restrict__ src, uint32_t* __restrict__ dstA,
                       uint32_t* __restrict__ dstB) {
    __shared__ float s[128][36];
    int tid = threadIdx.x, r0 = blockIdx.x * 128, c0 = blockIdx.y * 32;
    load_tile(src, s, r0, c0, tid);
    __syncthreads();
    pack_tile_A(s, dstA, MROWS, r0, c0, tid >> 5, tid & 31);
    pack_tile_B(s, dstB, MROWS, r0, c0, tid >> 5, tid & 31);
}
// weights: z=0 -> Wk as A, z=1 -> Wq as B (one launch)
__global__ void pack_w(const float* __restrict__ Wk, const float* __restrict__ Wq,
                       uint32_t* __restrict__ dstA, uint32_t* __restrict__ dstB) {
    __shared__ float s[128][36];
    int tid = threadIdx.x, r0 = blockIdx.x * 128, c0 = blockIdx.y * 32;
    if (blockIdx.z == 0) {
        load_tile(Wk, s, r0, c0, tid);
        __syncthreads();
        pack_tile_A(s, dstA, D, r0, c0, tid >> 5, tid & 31);
    } else {
        load_tile(Wq, s, r0, c0, tid);
        __syncthreads();
        pack_tile_B(s, dstB, D, r0, c0, tid >> 5, tid & 31);
    }
}

// ---------------- small vector kernels ----------------
__global__ void vecs_kernel(const float* __restrict__ Wq, const float* __restrict__ Wk,
                            const float* __restrict__ bq, const float* __restrict__ bk) {
    int gw   = (blockIdx.x * blockDim.x + threadIdx.x) >> 5;
    int lane = threadIdx.x & 31;
    float acc = 0.f;
    if (gw < D) {
        const float* row = Wq + (size_t)gw * D;
        for (int k = lane; k < D; k += 32) acc += row[k] * bk[k];
        #pragma unroll
        for (int o = 16; o > 0; o >>= 1) acc += __shfl_down_sync(0xffffffffu, acc, o);
        if (lane == 0) g_w1[gw] = acc;
    } else if (gw < 2*D) {
        const float* row = Wk + (size_t)(gw - D) * D;
        for (int k = lane; k < D; k += 32) acc += row[k] * bq[k];
        #pragma unroll
        for (int o = 16; o > 0; o >>= 1) acc += __shfl_down_sync(0xffffffffu, acc, o);
        if (lane == 0) g_w2[gw - D] = acc;
    } else if (gw == 2*D) {
        for (int k = lane; k < D; k += 32) acc += bq[k] * bk[k];
        #pragma unroll
        for (int o = 16; o > 0; o >>= 1) acc += __shfl_down_sync(0xffffffffu, acc, o);
        if (lane == 0) g_c0 = acc;
    }
}

__global__ void rows_kernel(const float* __restrict__ x, const float* __restrict__ Wo,
                            const float* __restrict__ bo) {
    int gw   = (blockIdx.x * blockDim.x + threadIdx.x) >> 5;
    int lane = threadIdx.x & 31;
    if (gw >= MROWS) return;
    const float* row = x + (size_t)gw * D;
    float ss = 0.f, pp = 0.f, qq = 0.f;
    for (int k = lane; k < D; k += 32) {
        float xv = row[k];
        ss += xv * Wo[k];
        pp += xv * g_w1[k];
        qq += xv * g_w2[k];
    }
    #pragma unroll
    for (int o = 16; o > 0; o >>= 1) {
        ss += __shfl_down_sync(0xffffffffu, ss, o);
        pp += __shfl_down_sync(0xffffffffu, pp, o);
        qq += __shfl_down_sync(0xffffffffu, qq, o);
    }
    if (lane == 0) {
        const float scale = 0.03125f;
        g_u[gw] = tanhf(ss + bo[0]);
        g_P[gw] = scale * (pp + g_c0);
        g_Q[gw] = scale * qq;
    }
}

// ---- fp16 GEMM: A via smem (cp.async, 3 stages), B via direct LDG from L2 with
//      distance-3 register prefetch (ring of 4 slots; slot = slab mod 4).
// MODE 0: write C as B-packed fp16 (R_out = D).     [Wm']
// MODE 1: write C as A-packed fp16 (R_out = MROWS). [T]
// MODE 2: fused epilogue, row-major fp32 out (streaming stores), batched by z.
template<int MODE>
__global__ void __launch_bounds__(THREADS, 2) mm_kernel(
    const uint32_t* __restrict__ Apk, const uint32_t* __restrict__ Bpk,
    void* __restrict__ Cout, int strideA, int strideB)
{
    constexpr int KSLAB_A = (BMT / 16) * 128;   // 1024 words per k16-slab
    constexpr int ATW = 4 * KSLAB_A;            // BK=64 -> 4 slabs = 16KB/stage
    constexpr int TN = 8;                       // 2x2 warp grid, 64x64 warp tile

    extern __shared__ uint32_t sm[];
    const int tid = threadIdx.x, w = tid >> 5, lane = tid & 31;
    const int wm = (w >> 1) * 64;
    const int wn = (w & 1) * 64;
    const int zrow = (MODE == 2) ? blockIdx.z * NSEQ : 0;
    const int m0 = blockIdx.y * BMT, n0 = blockIdx.x * BN;

    const uint32_t* Abase = Apk + (size_t)((zrow + m0) >> 4) * 128;
    const int mblk0 = wm >> 4, nblk0 = wn >> 3;
    const uint32_t* Bf = Bpk + (size_t)((zrow + n0) >> 3) * 64 + nblk0 * 64 + lane * 2;
    uint32_t smbase = (uint32_t)__cvta_generic_to_shared(sm);

    float acc[4][TN][4] = {};
    uint32_t bfr[4][TN][2];                      // B frag ring, slot = slab & 3

    auto ldB = [&](int slot, int slab) {
        const uint32_t* p = Bf + (size_t)slab * strideB;
        #pragma unroll
        for (int tn = 0; tn < TN; tn++)
            *(uint2*)bfr[slot][tn] = __ldg((const uint2*)(p + tn * 64));
    };

    auto issueA = [&](int it, int st) {
        uint32_t sb = smbase + (uint32_t)(st * ATW) * 4u;
        constexpr int ACH = KSLAB_A / 4;        // 256 16B-chunks per slab
        #pragma unroll
        for (int j = 0; j < (4 * ACH) / THREADS; j++) {
            int idx = tid + j * THREADS;
            int kk = idx / ACH, off = idx % ACH;
            cp16(sb + (uint32_t)(kk * KSLAB_A + off * 4) * 4u,
                 Abase + (size_t)(it * 4 + kk) * strideA + off * 4);
        }
        asm volatile("cp.async.commit_group;" ::: "memory");
    };

    issueA(0, 0);
    issueA(1, 1);
    ldB(0, 0);
    ldB(1, 1);
    ldB(2, 2);

    for (int it = 0; it < NITER; it++) {
        int st = it % STAGES;
        if (it < NITER - 1) asm volatile("cp.async.wait_group 1;" ::: "memory");
        else                asm volatile("cp.async.wait_group 0;" ::: "memory");
        __syncthreads();
        if (it + 2 < NITER) issueA(it + 2, (it + 2) % STAGES);
        const uint32_t* base = sm + st * ATW;
        #pragma unroll
        for (int ks = 0; ks < 4; ks++) {
            // prefetch B for slab+3 into slot (ks+3)&3 (last used at slab-1, drained)
            int pf = it * 4 + ks + 3;
            if (pf > NSLAB - 1) pf = NSLAB - 1;
            ldB((ks + 3) & 3, pf);
            uint32_t afr[4][4];
            #pragma unroll
            for (int tm = 0; tm < 4; tm++)
                *(uint4*)afr[tm] = *(const uint4*)&base[ks * KSLAB_A + (mblk0 + tm) * 128 + lane * 4];
            #pragma unroll
            for (int tm = 0; tm < 4; tm++)
                #pragma unroll
                for (int tn = 0; tn < TN; tn++)
                    mma_f16(acc[tm][tn], afr[tm], bfr[ks & 3][tn]);
        }
        // no trailing barrier: issueA(it+2) targets stage (it-1)%3, already drained
        // by every warp having passed this iteration's top barrier.
    }

    // ---- epilogue ----
    if (MODE == 0) {
        // B-packed fp16 out, n = r, k = c
        uint32_t* Cd = (uint32_t*)Cout;
        #pragma unroll
        for (int tm = 0; tm < 4; tm++)
            #pragma unroll
            for (int tn = 0; tn < TN; tn++) {
                int r = m0 + wm + tm * 16 + (lane >> 2);
                int c = n0 + wn + tn * 8 + (lane & 3) * 2;
                uint32_t w0 = f2h2(acc[tm][tn][0], acc[tm][tn][1]);
                uint32_t w1 = f2h2(acc[tm][tn][2], acc[tm][tn][3]);
                size_t kslab = (size_t)(c >> 4) * (D / 8) * 64;
                int sub = ((c & 7) >> 1) * 2 + ((c >> 3) & 1);
                int r8 = r + 8;
                Cd[kslab + (size_t)(r  >> 3) * 64 + (r  & 7) * 8 + sub] = w0;
                Cd[kslab + (size_t)(r8 >> 3) * 64 + (r8 & 7) * 8 + sub] = w1;
            }
    } else if (MODE == 1) {
        // A-packed fp16 out, m = r, k = c
        uint32_t* Cd = (uint32_t*)Cout;
        #pragma unroll
        for (int tm = 0; tm < 4; tm++)
            #pragma unroll
            for (int tn = 0; tn < TN; tn++) {
                int r = m0 + wm + tm * 16 + (lane >> 2);
                int c = n0 + wn + tn * 8 + (lane & 3) * 2;
                uint32_t w0 = f2h2(acc[tm][tn][0], acc[tm][tn][1]);
                uint32_t w1 = f2h2(acc[tm][tn][2], acc[tm][tn][3]);
                size_t kslab = (size_t)(c >> 4) * (MROWS / 16) * 128;
                int sub = ((c & 7) >> 1) * 4 + ((c & 8) >> 3) * 2;
                int r8 = r + 8;
                Cd[kslab + (size_t)(r  >> 4) * 128 + (r  & 7) * 16 + sub + ((r  & 8) >> 3)] = w0;
                Cd[kslab + (size_t)(r8 >> 4) * 128 + (r8 & 7) * 16 + sub + ((r8 & 8) >> 3)] = w1;
            }
    } else {
        float* C = (float*)Cout;
        float* sQ = (float*)sm;
        float* sU = sQ + BN;
        int jg0 = zrow + n0;
        __syncthreads();
        if (tid < BN) { sQ[tid] = g_Q[jg0 + tid]; sU[tid] = g_u[jg0 + tid]; }
        __syncthreads();
        const float scale = 0.03125f;
        size_t zr = (size_t)zrow;
        #pragma unroll
        for (int tm = 0; tm < 4; tm++) {
            int rloc0 = m0 + wm + tm * 16 + (lane >> 2);
            int rg0 = (int)zr + rloc0;
            float P0 = g_P[rg0],     u0 = g_u[rg0];
            float P1 = g_P[rg0 + 8], u1 = g_u[rg0 + 8];
            float* c0p = C + (zr + rloc0) * (size_t)NSEQ + n0;
            float* c1p = C + (zr + rloc0 + 8) * (size_t)NSEQ + n0;
            #pragma unroll
            for (int tn = 0; tn < TN; tn++) {
                int jl = wn + tn * 8 + (lane & 3) * 2;
                float qa = sQ[jl],   ua = sU[jl];
                float qb = sQ[jl+1], ub = sU[jl+1];
                float v00 = fmaf(scale, acc[tm][tn][0], P0 + qa)
                          + 5.f * (ua - u0) * frcp(fmaf(-u0, ua, 1.f));
                float v01 = fmaf(scale, acc[tm][tn][1], P0 + qb)
                          + 5.f * (ub - u0) * frcp(fmaf(-u0, ub, 1.f));
                float v10 = fmaf(scale, acc[tm][tn][2], P1 + qa)
                          + 5.f * (ua - u1) * frcp(fmaf(-u1, ua, 1.f));
                float v11 = fmaf(scale, acc[tm][tn][3], P1 + qb)
                          + 5.f * (ub - u1) * frcp(fmaf(-u1, ub, 1.f));
                // streaming stores: output is write-once, never re-read — evict-first
                // keeps TA/xB operand tiles resident in L2.
                __stcs((float2*)(c0p + jl), make_float2(v00, v01));
                __stcs((float2*)(c1p + jl), make_float2(v10, v11));
            }
        }
    }
}

// ---------------- launch (multi-stream DAG, monolithic GEMMs) ----------------
extern "C" void kernel_launch(void* const* d_in, const int* in_sizes, int n_in,
                              void* d_out, int out_size) {
    const float* x  = (const float*)d_in[0];
    const float* Wq = (const float*)d_in[1];
    const float* bq = (const float*)d_in[2];
    const float* Wk = (const float*)d_in[3];
    const float* bk = (const float*)d_in[4];
    const float* Wo = (const float*)d_in[5];
    const float* bo = (const float*)d_in[6];
    float* out = (float*)d_out;

    uint32_t *pxA, *pxB, *pWkA, *pWqB, *pWmB, *pTA;
    cudaGetSymbolAddress((void**)&pxA,  g_xA);
    cudaGetSymbolAddress((void**)&pxB,  g_xB);
    cudaGetSymbolAddress((void**)&pWkA, g_WkA);
    cudaGetSymbolAddress((void**)&pWqB, g_WqB);
    cudaGetSymbolAddress((void**)&pWmB, g_WmB);
    cudaGetSymbolAddress((void**)&pTA,  g_TA);

    const int SMK = STAGES * 4 * (BMT/16) * 128 * 4;  // 49152 (A stages only)
    static bool attr_done = false;
    if (!attr_done) {
        cudaFuncSetAttribute(mm_kernel<0>, cudaFuncAttributeMaxDynamicSharedMemorySize, SMK);
        cudaFuncSetAttribute(mm_kernel<1>, cudaFuncAttributeMaxDynamicSharedMemorySize, SMK);
        cudaFuncSetAttribute(mm_kernel<2>, cudaFuncAttributeMaxDynamicSharedMemorySize, SMK);
        attr_done = true;
    }

    // side streams + events for capture-safe fork/join (created once; first call is
    // the uncaptured correctness run; every call records the identical DAG)
    static cudaStream_t s1 = nullptr, s2 = nullptr;
    static cudaEvent_t  eRoot = nullptr, eG0 = nullptr, ePX = nullptr;
    if (!s1) {
        cudaStreamCreateWithFlags(&s1, cudaStreamNonBlocking);
        cudaStreamCreateWithFlags(&s2, cudaStreamNonBlocking);
        cudaEventCreateWithFlags(&eRoot, cudaEventDisableTiming);
        cudaEventCreateWithFlags(&eG0,   cudaEventDisableTiming);
        cudaEventCreateWithFlags(&ePX,   cudaEventDisableTiming);
    }
    cudaStream_t s0 = 0;   // harness (capture) stream

    // fork
    cudaEventRecord(eRoot, s0);
    cudaStreamWaitEvent(s1, eRoot, 0);
    cudaStreamWaitEvent(s2, eRoot, 0);

    // branch 1: weight pack -> GEMM0 (Wm' = Wk @ Wq^T, B-packed)
    pack_w<<<dim3(D/128, D/32, 2), 256, 0, s1>>>(Wk, Wq, pWkA, pWqB);
    mm_kernel<0><<<dim3(D/BN, D/BMT), THREADS, SMK, s1>>>(pWkA, pWqB, pWmB, D*8, D*8);
    cudaEventRecord(eG0, s1);

    // branch 2: x pack (both layouts)
    pack_x<<<dim3(MROWS/128, D/32), 256, 0, s2>>>(x, pxA, pxB);
    cudaEventRecord(ePX, s2);

    // main: bias precompute (vecs -> rows)
    vecs_kernel<<<257, 256, 0, s0>>>(Wq, Wk, bq, bk);
    rows_kernel<<<1024, 256, 0, s0>>>(x, Wo, bo);

    // join: GEMM1 needs GEMM0 + pack_x(A); GEMM2 additionally needs rows (main-ordered)
    cudaStreamWaitEvent(s0, eG0, 0);
    cudaStreamWaitEvent(s0, ePX, 0);

    // T = x @ Wm (via Wm' as B), written A-packed
    mm_kernel<1><<<dim3(D/BN, MROWS/BMT), THREADS, SMK, s0>>>(pxA, pWmB, pTA, MROWS*8, D*8);
    // out[b,i,j] = scale*(T_b[i,:].x_b[j,:]) + P_i + Q_j + 5*tanh-identity
    mm_kernel<2><<<dim3(NSEQ/BN, NSEQ/BMT, BATCH), THREADS, SMK, s0>>>(
        pTA, pxB, out, MROWS*8, MROWS*8);
}